// round 16
// baseline (speedup 1.0000x reference)
#include <cuda_runtime.h>
#include <cuda_fp16.h>
#include <cstdint>

#define LATENT 128
#define DQ 32            // KQ_DIM
#define BATCH 8
#define NN 16384
#define KK 16
#define ROWS (BATCH * NN)            // 131072
#define BNK  (BATCH * NN * KK)       // 2097152

#define PROJ_BLK_PER_B 64            // 64 blocks x 256 rows = 16384 rows/batch
#define AFF_BLK_PER_B  2048          // 2048 blocks x 128 logits = 262144 logits/batch
#define SEG (PROJ_BLK_PER_B + AFF_BLK_PER_B)   // 2112 blocks per batch segment

// combined projection table, fp16: row r has 64 halves = ks[0:32) | qs[32:64)
__device__ __align__(128) __half g_kq[ROWS * 64];
__device__ int g_idx_is64;
__device__ unsigned g_done[BATCH];   // per-batch proj completion counters

typedef unsigned u32;

__device__ __forceinline__ u32 cvt_f16x2(float hi, float lo) {
    u32 r;
    asm("cvt.rn.f16x2.f32 %0, %1, %2;" : "=r"(r) : "f"(hi), "f"(lo));
    return r;
}

__device__ __forceinline__ void mma_f16(float* d,
                                        u32 a0, u32 a1, u32 a2, u32 a3,
                                        u32 b0, u32 b1) {
    asm volatile(
        "mma.sync.aligned.m16n8k16.row.col.f32.f16.f16.f32 "
        "{%0,%1,%2,%3}, {%4,%5,%6,%7}, {%8,%9}, {%0,%1,%2,%3};"
        : "+f"(d[0]), "+f"(d[1]), "+f"(d[2]), "+f"(d[3])
        : "r"(a0), "r"(a1), "r"(a2), "r"(a3), "r"(b0), "r"(b1));
}

__device__ __forceinline__ u32 ld_acquire(const u32* p) {
    u32 v;
    asm volatile("ld.acquire.gpu.global.u32 %0, [%1];" : "=r"(v) : "l"(p) : "memory");
    return v;
}

__global__ void reset_kernel()
{
    if (threadIdx.x < BATCH) g_done[threadIdx.x] = 0;
}

// ---------------------------------------------------------------------------
// Fused pipeline kernel. Block layout (per batch segment of 2112 blocks):
//   s in [0,64):    PROJ block  -- 8 warps x 32 rows = 256 rows of batch b
//   s in [64,2112): AFFINITY block -- 128 logits of batch b; spins until
//                   g_done[b]==64 (acquire), i.e. batch b's table is complete.
// GPU dispatches blocks in index order, so aff(b) overlaps proj(b+1): the
// DRAM-bound projection streams while the L2-bound gather phase runs.
//
// PROJ: single-pass fp16 m16n8k16 MMA, k-permuted fragments (thread tig's A
// fragment = one contiguous float4 at k0 = ks*16+4*tig; B smem holds the
// matching permuted weights, conflict-free bank = 4g+tig), depth-2 prefetch.
// Writers: stores + __threadfence() + one atomicAdd(g_done[b]) per block.
// Block 0 also detects index dtype (odd 32-bit words of small nonneg int64
// are all zero; impossible for 256 genuine int32 indices).
//
// AFFINITY (round-8 best-measured form): 4 lanes per logit, 2 logits per
// 4-lane group (4 independent 16B gathers in flight), 2x shfl_xor reduce,
// lane 0 stores float2.
// ---------------------------------------------------------------------------
#define WST 68   // shared stride in u32 for weight pair array

__global__ void __launch_bounds__(256)
fused_kernel(const float* __restrict__ features,
             const float* __restrict__ ks_w, const float* __restrict__ ks_b,
             const float* __restrict__ qs_w, const float* __restrict__ qs_b,
             const void*  __restrict__ indices_raw,
             float*       __restrict__ out)
{
    int batch = blockIdx.x / SEG;
    int s     = blockIdx.x - batch * SEG;

    if (s < PROJ_BLK_PER_B) {
        // ================= PROJ =================
        if (blockIdx.x == 0 && threadIdx.x < 32) {
            const int* idx32 = (const int*)indices_raw;
            int lane = threadIdx.x;
            int all_hi_zero = 1;
            for (int i = lane; i < 256; i += 32)
                if (idx32[2 * i + 1] != 0) all_hi_zero = 0;
            all_hi_zero = __all_sync(0xffffffffu, all_hi_zero);
            if (lane == 0) g_idx_is64 = all_hi_zero;
        }

        __shared__ u32 whp[64 * WST];
        __shared__ float bsh[64];

        for (int i = threadIdx.x; i < 64 * 32; i += 256) {
            int n  = i >> 5;
            int j  = i & 31;              // j = ks*4 + tig
            int ksx = j >> 2;
            int tg  = j & 3;
            int k0  = ksx * 16 + 4 * tg;
            const float* src = (n < 32) ? (ks_w + n * LATENT)
                                        : (qs_w + (n - 32) * LATENT);
            float4 w = *reinterpret_cast<const float4*>(src + k0);
            whp[n * WST + ksx * 8 + tg]     = cvt_f16x2(w.y, w.x);
            whp[n * WST + ksx * 8 + tg + 4] = cvt_f16x2(w.w, w.z);
        }
        if (threadIdx.x < 32) {
            bsh[threadIdx.x]      = ks_b[threadIdx.x];
            bsh[threadIdx.x + 32] = qs_b[threadIdx.x];
        }
        __syncthreads();

        int warp = threadIdx.x >> 5;
        int lane = threadIdx.x & 31;
        int g    = lane >> 2;
        int tig  = lane & 3;

        int rb = batch * NN + s * 256 + warp * 32;

        float D[2][8][4];
#pragma unroll
        for (int nt = 0; nt < 8; nt++) {
            float b0 = bsh[nt * 8 + 2 * tig];
            float b1 = bsh[nt * 8 + 2 * tig + 1];
#pragma unroll
            for (int mt = 0; mt < 2; mt++) {
                D[mt][nt][0] = b0; D[mt][nt][1] = b1;
                D[mt][nt][2] = b0; D[mt][nt][3] = b1;
            }
        }

        const float* rp[4];
        rp[0] = features + (size_t)(rb      + g) * LATENT;
        rp[1] = features + (size_t)(rb + 8  + g) * LATENT;
        rp[2] = features + (size_t)(rb + 16 + g) * LATENT;
        rp[3] = features + (size_t)(rb + 24 + g) * LATENT;

        float4 fbuf[2][4];
        {
            int k0a = 4 * tig;
            int k0b = 16 + 4 * tig;
#pragma unroll
            for (int r = 0; r < 4; r++) {
                fbuf[0][r] = *reinterpret_cast<const float4*>(rp[r] + k0a);
                fbuf[1][r] = *reinterpret_cast<const float4*>(rp[r] + k0b);
            }
        }

#pragma unroll
        for (int ks = 0; ks < 8; ks++) {
            int cur = ks & 1;
            u32 a[2][4];
#pragma unroll
            for (int mt = 0; mt < 2; mt++) {
                float4 f0 = fbuf[cur][2 * mt];
                float4 f1 = fbuf[cur][2 * mt + 1];
                a[mt][0] = cvt_f16x2(f0.y, f0.x);
                a[mt][1] = cvt_f16x2(f1.y, f1.x);
                a[mt][2] = cvt_f16x2(f0.w, f0.z);
                a[mt][3] = cvt_f16x2(f1.w, f1.z);
            }
            if (ks < 6) {
                int k0 = (ks + 2) * 16 + 4 * tig;
#pragma unroll
                for (int r = 0; r < 4; r++)
                    fbuf[cur][r] = *reinterpret_cast<const float4*>(rp[r] + k0);
            }
#pragma unroll
            for (int nt = 0; nt < 8; nt++) {
                int base = (nt * 8 + g) * WST + ks * 8 + tig;
                u32 b0 = whp[base];
                u32 b1 = whp[base + 4];
#pragma unroll
                for (int mt = 0; mt < 2; mt++)
                    mma_f16(D[mt][nt], a[mt][0], a[mt][1], a[mt][2], a[mt][3], b0, b1);
            }
        }

#pragma unroll
        for (int mt = 0; mt < 2; mt++) {
            int row0 = rb + mt * 16 + g;
#pragma unroll
            for (int nt = 0; nt < 8; nt++) {
                __half2 h01 = __floats2half2_rn(D[mt][nt][0], D[mt][nt][1]);
                __half2 h23 = __floats2half2_rn(D[mt][nt][2], D[mt][nt][3]);
                *reinterpret_cast<__half2*>(
                    g_kq + (size_t)row0 * 64 + nt * 8 + 2 * tig) = h01;
                *reinterpret_cast<__half2*>(
                    g_kq + (size_t)(row0 + 8) * 64 + nt * 8 + 2 * tig) = h23;
            }
        }

        // publish: all stores visible, then signal this block done
        __threadfence();
        __syncthreads();
        if (threadIdx.x == 0)
            atomicAdd(&g_done[batch], 1u);

    } else {
        // ================= AFFINITY =================
        // wait for this batch's table
        if (threadIdx.x == 0) {
            while (ld_acquire(&g_done[batch]) < (u32)PROJ_BLK_PER_B)
                __nanosleep(128);
        }
        __syncthreads();

        int abid = batch * AFF_BLK_PER_B + (s - PROJ_BLK_PER_B);
        int t    = abid * 256 + threadIdx.x;
        int g    = t >> 2;                 // logit-pair id
        int sub  = t & 3;

        int lid0 = g << 1;
        int lid1 = lid0 | 1;

        long long x0, y0, x1, y1;
        if (g_idx_is64) {
            const long long* idx = (const long long*)indices_raw;
            x0 = idx[(size_t)BNK + lid0];
            x1 = idx[(size_t)BNK + lid1];
            y0 = idx[(size_t)2 * BNK + lid0];
            y1 = idx[(size_t)2 * BNK + lid1];
        } else {
            const int* idx = (const int*)indices_raw;
            x0 = idx[(size_t)BNK + lid0];
            x1 = idx[(size_t)BNK + lid1];
            y0 = idx[(size_t)2 * BNK + lid0];
            y1 = idx[(size_t)2 * BNK + lid1];
        }

        size_t base = (size_t)batch << 14;
        const uint4* px0 = reinterpret_cast<const uint4*>(g_kq + ((base + (size_t)x0) << 6)) + sub;
        const uint4* py0 = reinterpret_cast<const uint4*>(g_kq + ((base + (size_t)y0) << 6) + 32) + sub;
        const uint4* px1 = reinterpret_cast<const uint4*>(g_kq + ((base + (size_t)x1) << 6)) + sub;
        const uint4* py1 = reinterpret_cast<const uint4*>(g_kq + ((base + (size_t)y1) << 6) + 32) + sub;

        uint4 ax0 = *px0;
        uint4 ay0 = *py0;
        uint4 ax1 = *px1;
        uint4 ay1 = *py1;

        const __half2* hx0 = reinterpret_cast<const __half2*>(&ax0);
        const __half2* hy0 = reinterpret_cast<const __half2*>(&ay0);
        const __half2* hx1 = reinterpret_cast<const __half2*>(&ax1);
        const __half2* hy1 = reinterpret_cast<const __half2*>(&ay1);

        float s0 = 0.0f, s1 = 0.0f;
#pragma unroll
        for (int i = 0; i < 4; i++) {
            float2 fx0 = __half22float2(hx0[i]);
            float2 fy0 = __half22float2(hy0[i]);
            float2 fx1 = __half22float2(hx1[i]);
            float2 fy1 = __half22float2(hy1[i]);
            s0 = fmaf(fx0.x, fy0.x, s0);
            s0 = fmaf(fx0.y, fy0.y, s0);
            s1 = fmaf(fx1.x, fy1.x, s1);
            s1 = fmaf(fx1.y, fy1.y, s1);
        }

#pragma unroll
        for (int m = 2; m >= 1; m >>= 1) {
            s0 += __shfl_xor_sync(0xffffffffu, s0, m);
            s1 += __shfl_xor_sync(0xffffffffu, s1, m);
        }

        if (sub == 0) {
            float2 o = make_float2(s0 * 0.17677669529663687f,
                                   s1 * 0.17677669529663687f);  // 32^-0.5
            *reinterpret_cast<float2*>(out + lid0) = o;
        }
    }
}

extern "C" void kernel_launch(void* const* d_in, const int* in_sizes, int n_in,
                              void* d_out, int out_size)
{
    const float* features = (const float*)d_in[0];
    const float* ks_w     = (const float*)d_in[1];
    const float* ks_b     = (const float*)d_in[2];
    const float* qs_w     = (const float*)d_in[3];
    const float* qs_b     = (const float*)d_in[4];
    const void*  indices  = d_in[5];
    float*       out      = (float*)d_out;

    reset_kernel<<<1, 32>>>();
    fused_kernel<<<BATCH * SEG, 256>>>(features, ks_w, ks_b, qs_w, qs_b,
                                       indices, out);
}

// round 17
// speedup vs baseline: 4.4287x; 4.4287x over previous
#include <cuda_runtime.h>
#include <cuda_fp16.h>
#include <cstdint>

#define LATENT 128
#define DQ 32            // KQ_DIM
#define BATCH 8
#define NN 16384
#define KK 16
#define ROWS (BATCH * NN)            // 131072
#define BNK  (BATCH * NN * KK)       // 2097152

// combined projection table, fp16: row r has 64 halves = ks[0:32) | qs[32:64)
__device__ __align__(128) __half g_kq[ROWS * 64];
__device__ int g_idx_is64;

typedef unsigned u32;

__device__ __forceinline__ u32 cvt_f16x2(float hi, float lo) {
    u32 r;
    asm("cvt.rn.f16x2.f32 %0, %1, %2;" : "=r"(r) : "f"(hi), "f"(lo));
    return r;
}

__device__ __forceinline__ void mma_f16(float* d,
                                        u32 a0, u32 a1, u32 a2, u32 a3,
                                        u32 b0, u32 b1) {
    asm volatile(
        "mma.sync.aligned.m16n8k16.row.col.f32.f16.f16.f32 "
        "{%0,%1,%2,%3}, {%4,%5,%6,%7}, {%8,%9}, {%0,%1,%2,%3};"
        : "+f"(d[0]), "+f"(d[1]), "+f"(d[2]), "+f"(d[3])
        : "r"(a0), "r"(a1), "r"(a2), "r"(a3), "r"(b0), "r"(b1));
}

// ---------------------------------------------------------------------------
// Phase 1 (round-15 proven kernel + row_base param): single-pass fp16
// m16n8k16 tensor GEMM, k-permuted fragments (thread tig's A fragment = one
// contiguous float4 at k0 = ks*16+4*tig; B smem holds matching permuted
// weights, conflict-free bank = 4g+tig), depth-2 prefetch, 8 warps x 32 rows.
// Block 0 / warp 0 (DO_DETECT) detects index dtype.
// ---------------------------------------------------------------------------
#define WST 68   // shared stride in u32 for weight pair array

template <bool DO_DETECT>
__global__ void __launch_bounds__(256)
proj_mma_kernel(const float* __restrict__ features,
                const float* __restrict__ ks_w, const float* __restrict__ ks_b,
                const float* __restrict__ qs_w, const float* __restrict__ qs_b,
                const int*   __restrict__ idx32, int row_base)
{
    if (DO_DETECT && blockIdx.x == 0 && threadIdx.x < 32) {
        int lane = threadIdx.x;
        int all_hi_zero = 1;
        for (int i = lane; i < 256; i += 32)
            if (idx32[2 * i + 1] != 0) all_hi_zero = 0;
        all_hi_zero = __all_sync(0xffffffffu, all_hi_zero);
        if (lane == 0) g_idx_is64 = all_hi_zero;
    }

    __shared__ u32 whp[64 * WST];
    __shared__ float bsh[64];

    for (int i = threadIdx.x; i < 64 * 32; i += 256) {
        int n  = i >> 5;
        int j  = i & 31;
        int ksx = j >> 2;
        int tg  = j & 3;
        int k0  = ksx * 16 + 4 * tg;
        const float* src = (n < 32) ? (ks_w + n * LATENT) : (qs_w + (n - 32) * LATENT);
        float4 w = *reinterpret_cast<const float4*>(src + k0);
        whp[n * WST + ksx * 8 + tg]     = cvt_f16x2(w.y, w.x);
        whp[n * WST + ksx * 8 + tg + 4] = cvt_f16x2(w.w, w.z);
    }
    if (threadIdx.x < 32) {
        bsh[threadIdx.x]      = ks_b[threadIdx.x];
        bsh[threadIdx.x + 32] = qs_b[threadIdx.x];
    }
    __syncthreads();

    int warp = threadIdx.x >> 5;
    int lane = threadIdx.x & 31;
    int g    = lane >> 2;
    int tig  = lane & 3;

    int rb = row_base + (blockIdx.x * 8 + warp) * 32;

    float D[2][8][4];
#pragma unroll
    for (int nt = 0; nt < 8; nt++) {
        float b0 = bsh[nt * 8 + 2 * tig];
        float b1 = bsh[nt * 8 + 2 * tig + 1];
#pragma unroll
        for (int mt = 0; mt < 2; mt++) {
            D[mt][nt][0] = b0; D[mt][nt][1] = b1;
            D[mt][nt][2] = b0; D[mt][nt][3] = b1;
        }
    }

    const float* rp[4];
    rp[0] = features + (size_t)(rb      + g) * LATENT;
    rp[1] = features + (size_t)(rb + 8  + g) * LATENT;
    rp[2] = features + (size_t)(rb + 16 + g) * LATENT;
    rp[3] = features + (size_t)(rb + 24 + g) * LATENT;

    float4 fbuf[2][4];
    {
        int k0a = 4 * tig;
        int k0b = 16 + 4 * tig;
#pragma unroll
        for (int r = 0; r < 4; r++) {
            fbuf[0][r] = *reinterpret_cast<const float4*>(rp[r] + k0a);
            fbuf[1][r] = *reinterpret_cast<const float4*>(rp[r] + k0b);
        }
    }

#pragma unroll
    for (int ks = 0; ks < 8; ks++) {
        int cur = ks & 1;
        u32 a[2][4];
#pragma unroll
        for (int mt = 0; mt < 2; mt++) {
            float4 f0 = fbuf[cur][2 * mt];
            float4 f1 = fbuf[cur][2 * mt + 1];
            a[mt][0] = cvt_f16x2(f0.y, f0.x);
            a[mt][1] = cvt_f16x2(f1.y, f1.x);
            a[mt][2] = cvt_f16x2(f0.w, f0.z);
            a[mt][3] = cvt_f16x2(f1.w, f1.z);
        }
        if (ks < 6) {
            int k0 = (ks + 2) * 16 + 4 * tig;
#pragma unroll
            for (int r = 0; r < 4; r++)
                fbuf[cur][r] = *reinterpret_cast<const float4*>(rp[r] + k0);
        }
#pragma unroll
        for (int nt = 0; nt < 8; nt++) {
            int base = (nt * 8 + g) * WST + ks * 8 + tig;
            u32 b0 = whp[base];
            u32 b1 = whp[base + 4];
#pragma unroll
            for (int mt = 0; mt < 2; mt++)
                mma_f16(D[mt][nt], a[mt][0], a[mt][1], a[mt][2], a[mt][3], b0, b1);
        }
    }

#pragma unroll
    for (int mt = 0; mt < 2; mt++) {
        int row0 = rb + mt * 16 + g;
#pragma unroll
        for (int nt = 0; nt < 8; nt++) {
            __half2 h01 = __floats2half2_rn(D[mt][nt][0], D[mt][nt][1]);
            __half2 h23 = __floats2half2_rn(D[mt][nt][2], D[mt][nt][3]);
            *reinterpret_cast<__half2*>(
                g_kq + (size_t)row0 * 64 + nt * 8 + 2 * tig) = h01;
            *reinterpret_cast<__half2*>(
                g_kq + (size_t)(row0 + 8) * 64 + nt * 8 + 2 * tig) = h23;
        }
    }
}

// ---------------------------------------------------------------------------
// Phase 2 (round-8 proven kernel + pair_base param): 4 lanes per logit, 2
// logits per 4-lane group (4 independent 16B gathers in flight), 2x shfl_xor
// reduce, lane 0 stores float2.
// ---------------------------------------------------------------------------
__global__ void __launch_bounds__(256)
affinity_kernel(const void* __restrict__ indices_raw, float* __restrict__ out,
                int pair_base)
{
    int t   = blockIdx.x * 256 + threadIdx.x;
    int g   = pair_base + (t >> 2);   // logit-pair id
    int sub = t & 3;

    int lid0 = g << 1;
    int lid1 = lid0 | 1;
    int b    = lid0 >> 18;            // N*K = 2^18 (pair shares batch)

    long long x0, y0, x1, y1;
    if (g_idx_is64) {
        const long long* idx = (const long long*)indices_raw;
        x0 = idx[(size_t)BNK + lid0];
        x1 = idx[(size_t)BNK + lid1];
        y0 = idx[(size_t)2 * BNK + lid0];
        y1 = idx[(size_t)2 * BNK + lid1];
    } else {
        const int* idx = (const int*)indices_raw;
        x0 = idx[(size_t)BNK + lid0];
        x1 = idx[(size_t)BNK + lid1];
        y0 = idx[(size_t)2 * BNK + lid0];
        y1 = idx[(size_t)2 * BNK + lid1];
    }

    size_t base = (size_t)b << 14;
    const uint4* px0 = reinterpret_cast<const uint4*>(g_kq + ((base + (size_t)x0) << 6)) + sub;
    const uint4* py0 = reinterpret_cast<const uint4*>(g_kq + ((base + (size_t)y0) << 6) + 32) + sub;
    const uint4* px1 = reinterpret_cast<const uint4*>(g_kq + ((base + (size_t)x1) << 6)) + sub;
    const uint4* py1 = reinterpret_cast<const uint4*>(g_kq + ((base + (size_t)y1) << 6) + 32) + sub;

    uint4 ax0 = *px0;
    uint4 ay0 = *py0;
    uint4 ax1 = *px1;
    uint4 ay1 = *py1;

    const __half2* hx0 = reinterpret_cast<const __half2*>(&ax0);
    const __half2* hy0 = reinterpret_cast<const __half2*>(&ay0);
    const __half2* hx1 = reinterpret_cast<const __half2*>(&ax1);
    const __half2* hy1 = reinterpret_cast<const __half2*>(&ay1);

    float s0 = 0.0f, s1 = 0.0f;
#pragma unroll
    for (int i = 0; i < 4; i++) {
        float2 fx0 = __half22float2(hx0[i]);
        float2 fy0 = __half22float2(hy0[i]);
        float2 fx1 = __half22float2(hx1[i]);
        float2 fy1 = __half22float2(hy1[i]);
        s0 = fmaf(fx0.x, fy0.x, s0);
        s0 = fmaf(fx0.y, fy0.y, s0);
        s1 = fmaf(fx1.x, fy1.x, s1);
        s1 = fmaf(fx1.y, fy1.y, s1);
    }

#pragma unroll
    for (int m = 2; m >= 1; m >>= 1) {
        s0 += __shfl_xor_sync(0xffffffffu, s0, m);
        s1 += __shfl_xor_sync(0xffffffffu, s1, m);
    }

    if (sub == 0) {
        float2 o = make_float2(s0 * 0.17677669529663687f,
                               s1 * 0.17677669529663687f);  // 32^-0.5
        *reinterpret_cast<float2*>(out + lid0) = o;
    }
}

// ---- stream/event plumbing for the 2-stage graph pipeline ----
// Created once at static-init (host objects; no cudaMalloc-family calls).
namespace {
struct Pipe {
    cudaStream_t s2 = nullptr;
    cudaEvent_t evP0 = nullptr, evP1 = nullptr, evJ = nullptr;
    bool ok = false;
    Pipe() {
        ok = (cudaStreamCreateWithFlags(&s2, cudaStreamNonBlocking) == cudaSuccess)
          && (cudaEventCreateWithFlags(&evP0, cudaEventDisableTiming) == cudaSuccess)
          && (cudaEventCreateWithFlags(&evP1, cudaEventDisableTiming) == cudaSuccess)
          && (cudaEventCreateWithFlags(&evJ,  cudaEventDisableTiming) == cudaSuccess);
    }
};
Pipe g_pipe;
}

extern "C" void kernel_launch(void* const* d_in, const int* in_sizes, int n_in,
                              void* d_out, int out_size)
{
    const float* features = (const float*)d_in[0];
    const float* ks_w     = (const float*)d_in[1];
    const float* ks_b     = (const float*)d_in[2];
    const float* qs_w     = (const float*)d_in[3];
    const float* qs_b     = (const float*)d_in[4];
    const void*  indices  = d_in[5];
    float*       out      = (float*)d_out;

    const int HROWS  = ROWS / 2;      // 65536 rows per half
    const int HPAIRS = BNK / 4;       // 524288 logit-pairs per half
    const int PBLK   = HROWS / 256;   // 256 proj blocks per half
    const int ABLK   = HPAIRS * 4 / 256;  // 8192 aff blocks per half

    if (g_pipe.ok) {
        // half 0 projection on main stream
        proj_mma_kernel<true><<<PBLK, 256>>>(features, ks_w, ks_b, qs_w, qs_b,
                                             (const int*)indices, 0);
        cudaEventRecord(g_pipe.evP0, 0);
        cudaStreamWaitEvent(g_pipe.s2, g_pipe.evP0, 0);

        // half 1 projection on main stream (overlaps aff half 0 on s2)
        proj_mma_kernel<false><<<PBLK, 256>>>(features, ks_w, ks_b, qs_w, qs_b,
                                              (const int*)indices, HROWS);
        cudaEventRecord(g_pipe.evP1, 0);

        // aff half 0 on s2 (needs only proj half 0)
        affinity_kernel<<<ABLK, 256, 0, g_pipe.s2>>>(indices, out, 0);
        // aff half 1 on s2 (needs proj half 1)
        cudaStreamWaitEvent(g_pipe.s2, g_pipe.evP1, 0);
        affinity_kernel<<<ABLK, 256, 0, g_pipe.s2>>>(indices, out, HPAIRS);

        // join back to the main stream
        cudaEventRecord(g_pipe.evJ, g_pipe.s2);
        cudaStreamWaitEvent(0, g_pipe.evJ, 0);
    } else {
        // fallback: serial on one stream
        proj_mma_kernel<true><<<PBLK, 256>>>(features, ks_w, ks_b, qs_w, qs_b,
                                             (const int*)indices, 0);
        proj_mma_kernel<false><<<PBLK, 256>>>(features, ks_w, ks_b, qs_w, qs_b,
                                              (const int*)indices, HROWS);
        affinity_kernel<<<ABLK, 256>>>(indices, out, 0);
        affinity_kernel<<<ABLK, 256>>>(indices, out, HPAIRS);
    }
}